// round 2
// baseline (speedup 1.0000x reference)
#include <cuda_runtime.h>
#include <cuda_bf16.h>
#include <math_constants.h>

// Problem constants
#define BB 512
#define QQ 100
#define CC 81
#define VV 117
#define NQ (BB*QQ)            // 51200

// Output layout (flattened tuple, float32):
// hoi_scores [B,Q,V] | obj_labels [B,Q] | sub_boxes [B,Q,4] | obj_boxes [B,Q,4] | keep [B,Q]
#define OFF_HOI  0ull
#define OFF_LAB  ((unsigned long long)NQ * VV)                 // 5990400
#define OFF_SUB  (OFF_LAB + (unsigned long long)NQ)            // 6041600
#define OFF_OBJ  (OFF_SUB + (unsigned long long)NQ * 4)        // 6246400
#define OFF_KEEP (OFF_OBJ + (unsigned long long)NQ * 4)        // 6451200

// Scratch: per-query max hoi score for NMS
__device__ float g_maxsc[NQ];

// ---------------------------------------------------------------------------
// Kernel 1: per-query scoring + boxes. One warp per query, 4 warps per block.
// ---------------------------------------------------------------------------
__global__ __launch_bounds__(128)
void k1_score(const float* __restrict__ obj_logits,
              const float* __restrict__ verb_logits,
              const float* __restrict__ sub_in,
              const float* __restrict__ obj_in,
              const float* __restrict__ cmat,     // [V, C]
              const int* __restrict__ ts,         // [B, 2] (h, w) as int32
              float* __restrict__ out)
{
    const int warp = threadIdx.x >> 5;
    const int lane = threadIdx.x & 31;
    const int gq = blockIdx.x * 4 + warp;   // global query index
    if (gq >= NQ) return;
    const int b = gq / QQ;

    // ---- softmax over 81 obj logits; max/argmax over first 80 ----
    const float* ol = obj_logits + (size_t)gq * CC;
    float l0 = ol[lane];                                      // lane < 32 < 81
    float l1 = (lane + 32 < CC) ? ol[lane + 32] : -CUDART_INF_F;
    float l2 = (lane + 64 < CC) ? ol[lane + 64] : -CUDART_INF_F;

    float m = fmaxf(l0, fmaxf(l1, l2));
    #pragma unroll
    for (int o = 16; o; o >>= 1) m = fmaxf(m, __shfl_xor_sync(0xffffffffu, m, o));

    float s = expf(l0 - m);
    if (lane + 32 < CC) s += expf(l1 - m);
    if (lane + 64 < CC) s += expf(l2 - m);
    #pragma unroll
    for (int o = 16; o; o >>= 1) s += __shfl_xor_sync(0xffffffffu, s, o);

    // argmax over classes [0, 80): candidates per lane in increasing index
    float bv = l0; int bi = lane;                              // lane < 80 always
    if (lane + 32 < CC - 1 && l1 > bv) { bv = l1; bi = lane + 32; }
    if (lane + 64 < CC - 1 && l2 > bv) { bv = l2; bi = lane + 64; }
    #pragma unroll
    for (int o = 16; o; o >>= 1) {
        float ov = __shfl_xor_sync(0xffffffffu, bv, o);
        int   oi = __shfl_xor_sync(0xffffffffu, bi, o);
        if (ov > bv || (ov == bv && oi < bi)) { bv = ov; bi = oi; }
    }
    const float obj_score = expf(bv - m) / s;
    const int   label = bi;

    // ---- hoi scores = sigmoid(verb) * obj_score * correct_mat[v, label] ----
    const float* vl = verb_logits + (size_t)gq * VV;
    float* ho = out + OFF_HOI + (size_t)gq * VV;
    float mx = -CUDART_INF_F;
    #pragma unroll
    for (int v = lane; v < VV; v += 32) {
        float sig = 1.0f / (1.0f + expf(-vl[v]));
        float h = sig * obj_score * cmat[(size_t)v * CC + label];
        ho[v] = h;
        mx = fmaxf(mx, h);
    }
    #pragma unroll
    for (int o = 16; o; o >>= 1) mx = fmaxf(mx, __shfl_xor_sync(0xffffffffu, mx, o));

    if (lane == 0) {
        g_maxsc[gq] = mx;
        out[OFF_LAB + gq] = (float)label;
    }

    // ---- boxes: cxcywh -> xyxy, * [w,h,w,h] ----
    if (lane < 8) {
        const int kk = lane & 3;
        const float* bx = ((lane < 4) ? sub_in : obj_in) + (size_t)gq * 4;
        float c = bx[kk & 1];
        float d = bx[(kk & 1) + 2];
        float sc = (kk & 1) ? (float)ts[b * 2 + 0] : (float)ts[b * 2 + 1]; // h : w
        float val = ((kk < 2) ? (c - 0.5f * d) : (c + 0.5f * d)) * sc;
        out[((lane < 4) ? OFF_SUB : OFF_OBJ) + (size_t)gq * 4 + kk] = val;
    }
}

// ---------------------------------------------------------------------------
// Kernel 2: per-image pairwise NMS. One block (128 threads) per image.
// ---------------------------------------------------------------------------
__device__ __forceinline__ float pair_iou(float ax1, float ay1, float ax2, float ay2, float aA,
                                          float bx1, float by1, float bx2, float by2, float bA)
{
    float xx1 = fmaxf(ax1, bx1), yy1 = fmaxf(ay1, by1);
    float xx2 = fminf(ax2, bx2), yy2 = fminf(ay2, by2);
    float w = fmaxf(0.0f, xx2 - xx1 + 1.0f);
    float h = fmaxf(0.0f, yy2 - yy1 + 1.0f);
    float inter = w * h;
    return inter / (aA + bA - inter);
}

__global__ __launch_bounds__(128)
void k2_nms(float* __restrict__ out)
{
    const int b = blockIdx.x;
    const int tid = threadIdx.x;

    __shared__ float sc[QQ];
    __shared__ int   orig[QQ];
    __shared__ int   lab[QQ];
    __shared__ float sx1[QQ], sy1[QQ], sx2[QQ], sy2[QQ], sA[QQ];
    __shared__ float qx1[QQ], qy1[QQ], qx2[QQ], qy2[QQ], qA[QQ];
    __shared__ unsigned supmat[QQ][4];
    __shared__ unsigned suppw[4];

    if (tid < QQ) sc[tid] = g_maxsc[b * QQ + tid];
    for (int t = tid; t < QQ * 4; t += blockDim.x) ((unsigned*)supmat)[t] = 0u;
    __syncthreads();

    if (tid < QQ) {
        // stable descending rank (matches jnp.argsort(-scores), stable)
        float mine = sc[tid];
        int r = 0;
        #pragma unroll 4
        for (int j = 0; j < QQ; j++) {
            float o = sc[j];
            r += (o > mine) || (o == mine && j < tid);
        }
        const size_t base = (size_t)(b * QQ + tid) * 4;
        const float* sb = out + OFF_SUB + base;
        const float* ob = out + OFF_OBJ + base;
        float a1 = sb[0], a2 = sb[1], a3 = sb[2], a4 = sb[3];
        sx1[r] = a1; sy1[r] = a2; sx2[r] = a3; sy2[r] = a4;
        sA[r] = (a3 - a1 + 1.0f) * (a4 - a2 + 1.0f);
        float c1 = ob[0], c2 = ob[1], c3 = ob[2], c4 = ob[3];
        qx1[r] = c1; qy1[r] = c2; qx2[r] = c3; qy2[r] = c4;
        qA[r] = (c3 - c1 + 1.0f) * (c4 - c2 + 1.0f);
        lab[r]  = (int)out[OFF_LAB + b * QQ + tid];
        orig[r] = tid;
    }
    __syncthreads();

    // pairwise suppression matrix (upper triangular), as bitmasks
    for (int p = tid; p < QQ * QQ; p += blockDim.x) {
        int i = p / QQ;
        int j = p - i * QQ;
        if (j <= i) continue;
        if (lab[i] != lab[j]) continue;
        float iou_s = pair_iou(sx1[i], sy1[i], sx2[i], sy2[i], sA[i],
                               sx1[j], sy1[j], sx2[j], sy2[j], sA[j]);
        float iou_o = pair_iou(qx1[i], qy1[i], qx2[i], qy2[i], qA[i],
                               qx1[j], qy1[j], qx2[j], qy2[j], qA[j]);
        float ovr = iou_s * sqrtf(iou_o);     // ALPHA=1.0, BETA=0.5
        if (ovr > 0.7f)
            atomicOr(&supmat[i][j >> 5], 1u << (j & 31));
    }
    __syncthreads();

    // sequential greedy suppression, bit-parallel across 4 words
    if (tid == 0) {
        unsigned w0 = 0, w1 = 0, w2 = 0, w3 = 0;
        #pragma unroll 4
        for (int i = 0; i < QQ; i++) {
            unsigned wi = (i < 32) ? w0 : (i < 64) ? w1 : (i < 96) ? w2 : w3;
            if (!((wi >> (i & 31)) & 1u)) {
                w0 |= supmat[i][0];
                w1 |= supmat[i][1];
                w2 |= supmat[i][2];
                w3 |= supmat[i][3];
            }
        }
        suppw[0] = w0; suppw[1] = w1; suppw[2] = w2; suppw[3] = w3;
    }
    __syncthreads();

    if (tid < QQ) {
        bool suppressed = (suppw[tid >> 5] >> (tid & 31)) & 1u;
        out[OFF_KEEP + b * QQ + orig[tid]] = suppressed ? 0.0f : 1.0f;
    }
}

// ---------------------------------------------------------------------------
extern "C" void kernel_launch(void* const* d_in, const int* in_sizes, int n_in,
                              void* d_out, int out_size)
{
    const float* obj_logits  = (const float*)d_in[0];
    const float* verb_logits = (const float*)d_in[1];
    const float* sub_boxes   = (const float*)d_in[2];
    const float* obj_boxes   = (const float*)d_in[3];
    const float* correct_mat = (const float*)d_in[4];
    const int*   target_sz   = (const int*)d_in[5];
    float* out = (float*)d_out;

    k1_score<<<NQ / 4, 128>>>(obj_logits, verb_logits, sub_boxes, obj_boxes,
                              correct_mat, target_sz, out);
    k2_nms<<<BB, 128>>>(out);
}